// round 14
// baseline (speedup 1.0000x reference)
#include <cuda_runtime.h>
#include <cuda_fp16.h>
#include <math.h>
#include <stdint.h>

// ---------------------------------------------------------------------------
// Problem constants
// ---------------------------------------------------------------------------
namespace {
constexpr int Dm   = 768;
constexpr int FFm  = 3072;
constexpr int Hm   = 12;
constexpr int Lm   = 3;
constexpr int CSm  = 512;
constexpr int Bm   = 256;
constexpr int NSEQ = 16384;         // sequences of 2 tokens
constexpr int TT   = NSEQ * 2;      // 32768 tokens
constexpr float EPSf = 1e-5f;
constexpr int PS   = 72;            // smem row stride in halves (BK=64 + 8 pad)
constexpr int QKV  = 2304;          // fused QKV width
constexpr int NTHR = 128;           // gemm block: 4 warps, warp tile 64x64
}

// ---------------------------------------------------------------------------
// Scratch (device globals; no runtime allocation allowed)
// ---------------------------------------------------------------------------
__device__ float g_x [TT * Dm];                    // fp32 residual state
__device__ float g_peq[Lm * 3 * Dm];               // pe @ Wq^T per (layer,role)
__device__ float g_pek[Lm * 3 * Dm];               // pe @ Wk^T per (layer,role)
__device__ __align__(16) __half g_sc  [TT * CSm];  // score outs (half)
__device__ __align__(16) __half g_qkvh[TT * QKV];  // fused QKV / half delta
__device__ __align__(16) __half g_xh  [TT * Dm];   // half copy of x
__device__ __align__(16) __half g_ah  [TT * Dm];   // attn-out
__device__ __align__(16) __half g_sh  [16640 * Dm];// score-path hiddens (own buf)
__device__ __align__(16) __half g_hidh[TT * FFm];  // MLP hidden (half)
__device__ __align__(16) __half g_wh  [24182784];  // all weights, half
__device__ __align__(16) __half g_ch  [TT * Dm];   // child, half
__device__ __align__(16) __half g_ph  [Bm * Dm];   // parent, half

__device__ __forceinline__ float gelu_f(float x) {
    return 0.5f * x * (1.0f + erff(x * 0.7071067811865475f));
}

__device__ __forceinline__ void cp_async16(uint32_t s, const void* g) {
    asm volatile("cp.async.cg.shared.global [%0], [%1], 16;\n" :: "r"(s), "l"(g));
}
__device__ __forceinline__ void cp_commit() {
    asm volatile("cp.async.commit_group;\n");
}
template <int N> __device__ __forceinline__ void cp_wait() {
    asm volatile("cp.async.wait_group %0;\n" :: "n"(N));
}
__device__ __forceinline__ void ldsm4(uint32_t& r0, uint32_t& r1,
                                      uint32_t& r2, uint32_t& r3, uint32_t addr) {
    asm volatile("ldmatrix.sync.aligned.m8n8.x4.shared.b16 {%0,%1,%2,%3}, [%4];"
                 : "=r"(r0), "=r"(r1), "=r"(r2), "=r"(r3) : "r"(addr));
}
__device__ __forceinline__ void mma16816(float* c, const uint32_t* a, const uint32_t* b) {
    asm volatile(
        "mma.sync.aligned.m16n8k16.row.col.f32.f16.f16.f32 "
        "{%0,%1,%2,%3}, {%4,%5,%6,%7}, {%8,%9}, {%0,%1,%2,%3};"
        : "+f"(c[0]), "+f"(c[1]), "+f"(c[2]), "+f"(c[3])
        : "r"(a[0]), "r"(a[1]), "r"(a[2]), "r"(a[3]), "r"(b[0]), "r"(b[1]));
}

// ---------------------------------------------------------------------------
// GEMM body: CTA 128x128, 4 warps (2m x 2n), warp tile 64x64, BK=64,
// 3-stage cp.async pipeline, 2 CTAs/SM, DOUBLE-BUFFERED FRAGMENTS:
// ldsm for k-step ks+1 issues while the 32 HMMAs of ks execute, hiding
// LDS latency with only 2 warps/SMSP (R12's failure mode). Crossbar
// ceiling for this shape ~48% tensor (vs 40% for R11/R13 shape).
// ---------------------------------------------------------------------------
template <bool GELU, bool HALFOUT>
__device__ __forceinline__ void gemm_body(
    const __half* __restrict__ A, int lda,
    const __half* __restrict__ B, const float* __restrict__ bias,
    void* __restrict__ Cv, int ldc, int K, int bm, int bn, __half* sh)
{
    constexpr int BM = 128, BN = 128, BK = 64, ST = 3;
    constexpr int ASZ = BM * PS;
    constexpr int BSZ = BN * PS;
    __half* As = sh;
    __half* Bs = sh + ST * ASZ;

    const int tid  = threadIdx.x;
    const int lane = tid & 31;
    const int wid  = tid >> 5;             // 0..3
    const int wm   = wid >> 1;             // 0..1 : 64-row slab
    const int wn   = wid & 1;              // 0..1 : 64-col slab

    // staging: 16B chunks; A and B each 1024 chunks (8/thread each)
    const int r0 = tid >> 3;               // 0..15
    const int cc = (tid & 7) * 8;          // halves: 0..56
    const __half* Ap = A + (size_t)(bm + r0) * lda + cc;
    const __half* Bp = B + (size_t)(bn + r0) * K   + cc;

    const uint32_t sAbase = (uint32_t)__cvta_generic_to_shared(As);
    const uint32_t sBbase = (uint32_t)__cvta_generic_to_shared(Bs);
    const uint32_t sA = sAbase + (r0 * PS + cc) * 2;
    const uint32_t sB = sBbase + (r0 * PS + cc) * 2;

    const int nk = K / BK;

    auto issue = [&](int st, int kt) {
        const __half* Ag = Ap + kt * BK;
        const __half* Bg = Bp + kt * BK;
        uint32_t a = sA + st * (ASZ * 2);
        uint32_t b = sB + st * (BSZ * 2);
#pragma unroll
        for (int i = 0; i < 8; i++)
            cp_async16(a + i * 16 * PS * 2, Ag + (size_t)i * 16 * lda);
#pragma unroll
        for (int i = 0; i < 8; i++)
            cp_async16(b + i * 16 * PS * 2, Bg + (size_t)i * 16 * K);
        cp_commit();
    };

    float c[4][8][4];
#pragma unroll
    for (int mt = 0; mt < 4; mt++)
#pragma unroll
        for (int nt = 0; nt < 8; nt++)
#pragma unroll
            for (int j = 0; j < 4; j++) c[mt][nt][j] = 0.f;

    const int aOff = (wm * 64 + (lane & 15)) * PS + (lane >> 4) * 8;
    const int bOff = (wn * 64 + (lane & 7) + ((lane >> 4) & 1) * 8) * PS
                   + ((lane >> 3) & 1) * 8;

    issue(0, 0);
    issue(1, 1);

    uint32_t a[2][4][4], b[2][8][2];

    for (int it = 0; it < nk; it++) {
        cp_wait<1>();
        __syncthreads();
        if (it + 2 < nk) issue((it + 2) % 3, it + 2);
        else             cp_commit();

        const int st = it % 3;
        const uint32_t aS = sAbase + (st * ASZ) * 2;
        const uint32_t bS = sBbase + (st * BSZ) * 2;

        auto ldfrag = [&](int bufi, int ks) {
#pragma unroll
            for (int mt = 0; mt < 4; mt++)
                ldsm4(a[bufi][mt][0], a[bufi][mt][1], a[bufi][mt][2], a[bufi][mt][3],
                      aS + (aOff + mt * 16 * PS + ks * 16) * 2);
#pragma unroll
            for (int np = 0; np < 4; np++)
                ldsm4(b[bufi][2 * np][0], b[bufi][2 * np][1],
                      b[bufi][2 * np + 1][0], b[bufi][2 * np + 1][1],
                      bS + (bOff + np * 16 * PS + ks * 16) * 2);
        };

        ldfrag(0, 0);
#pragma unroll
        for (int ks = 0; ks < 4; ks++) {
            if (ks < 3) ldfrag((ks + 1) & 1, ks + 1);   // prefetch next k-step
            const int cur = ks & 1;
#pragma unroll
            for (int mt = 0; mt < 4; mt++)
#pragma unroll
                for (int nt = 0; nt < 8; nt++)
                    mma16816(c[mt][nt], a[cur][mt], b[cur][nt]);
        }
    }

    const int g  = lane >> 2;
    const int tg = lane & 3;
#pragma unroll
    for (int mt = 0; mt < 4; mt++) {
        const int row = bm + wm * 64 + mt * 16 + g;
#pragma unroll
        for (int nt = 0; nt < 8; nt++) {
            const int col = bn + wn * 64 + nt * 8 + 2 * tg;
            const float bx = bias[col], by = bias[col + 1];
            float v0x = c[mt][nt][0] + bx, v0y = c[mt][nt][1] + by;
            float v1x = c[mt][nt][2] + bx, v1y = c[mt][nt][3] + by;
            if (GELU) {
                v0x = gelu_f(v0x); v0y = gelu_f(v0y);
                v1x = gelu_f(v1x); v1y = gelu_f(v1y);
            }
            if (HALFOUT) {
                __half* C = (__half*)Cv;
                *(__half2*)(C + (size_t)row * ldc + col)       = __floats2half2_rn(v0x, v0y);
                *(__half2*)(C + (size_t)(row + 8) * ldc + col) = __floats2half2_rn(v1x, v1y);
            } else {
                float* C = (float*)Cv;
                *(float2*)(C + (size_t)row * ldc + col)       = make_float2(v0x, v0y);
                *(float2*)(C + (size_t)(row + 8) * ldc + col) = make_float2(v1x, v1y);
            }
        }
    }
}

template <bool GELU, bool HALFOUT>
__global__ void __launch_bounds__(NTHR, 2) hgemm(
    const __half* __restrict__ A, int lda,
    const __half* __restrict__ B, const float* __restrict__ bias,
    void* __restrict__ Cv, int ldc, int K)
{
    extern __shared__ __half sh[];
    gemm_body<GELU, HALFOUT>(A, lda, B, bias, Cv, ldc, K,
                             blockIdx.y * 128, blockIdx.x * 128, sh);
}

// 3-segment batched GEMM: blockIdx.y range selects (A,lda,B,bias,C)
template <bool GELU, bool HALFOUT>
__global__ void __launch_bounds__(NTHR, 2) hgemm_b3(
    const __half* A0, int lda0, const __half* B0, const float* bias0, void* C0,
    const __half* A1, int lda1, const __half* B1, const float* bias1, void* C1,
    const __half* A2, int lda2, const __half* B2, const float* bias2, void* C2,
    int y1, int y2, int ldc, int K)
{
    extern __shared__ __half sh[];
    const int y = blockIdx.y;
    const __half* A; int lda; const __half* B; const float* bias; void* C; int ly;
    if (y < y1)      { A = A0; lda = lda0; B = B0; bias = bias0; C = C0; ly = y; }
    else if (y < y2) { A = A1; lda = lda1; B = B1; bias = bias1; C = C1; ly = y - y1; }
    else             { A = A2; lda = lda2; B = B2; bias = bias2; C = C2; ly = y - y2; }
    gemm_body<GELU, HALFOUT>(A, lda, B, bias, C, ldc, K,
                             ly * 128, blockIdx.x * 128, sh);
}

// ---------------------------------------------------------------------------
// Fused fp32 -> fp16 conversion for all segments (single launch)
// ---------------------------------------------------------------------------
struct CvtArgs {
    const float2* src[12];
    __half2*      dst[12];
    int           end[12];
};
__global__ void cvt_all(CvtArgs a, int total2)
{
    int i = blockIdx.x * blockDim.x + threadIdx.x;
    if (i >= total2) return;
    int s = 0;
#pragma unroll
    for (int k = 0; k < 11; k++) s += (i >= a.end[s]) ? 1 : 0;
    int base = s ? a.end[s - 1] : 0;
    float2 v = a.src[s][i - base];
    a.dst[s][i - base] = __floats2half2_rn(v.x, v.y);
}

// ---------------------------------------------------------------------------
// pe-projection biases
// ---------------------------------------------------------------------------
__global__ void peb(const float* __restrict__ pos_emb,
                    const __half* __restrict__ w_aiw,
                    float* __restrict__ peq, float* __restrict__ pek)
{
    int gw   = (blockIdx.x * blockDim.x + threadIdx.x) >> 5;
    int lane = threadIdx.x & 31;
    if (gw >= 2 * Lm * 3 * Dm) return;
    int d  = gw % Dm;
    int t  = gw / Dm;
    int r  = t % 3;
    int qk = (t / 3) % 2;
    int l  = t / 6;

    const __half* wrow = w_aiw + ((size_t)l * 3 * Dm + qk * Dm + d) * Dm;
    const float*  pe   = pos_emb + (size_t)(l * 4 + r) * Dm;
    float s = 0.f;
#pragma unroll 4
    for (int j = lane; j < Dm; j += 32) s += pe[j] * __half2float(wrow[j]);
#pragma unroll
    for (int o = 16; o; o >>= 1) s += __shfl_xor_sync(0xffffffffu, s, o);
    if (lane == 0)
        (qk ? pek : peq)[(l * 3 + r) * Dm + d] = s;
}

// ---------------------------------------------------------------------------
// x construction
// ---------------------------------------------------------------------------
__global__ void build_x(const float* __restrict__ parent,
                        const float* __restrict__ child)
{
    int idx = blockIdx.x * blockDim.x + threadIdx.x;
    if (idx >= TT * Dm) return;
    int t = idx / Dm;
    int d = idx - t * Dm;
    int n = t >> 1;
    float val;
    if ((t & 1) == 0) {
        int b = n >> 6;
        val = parent[b * Dm + d];
    } else {
        val = child[(size_t)(n ^ 1) * Dm + d];
    }
    g_x[idx]  = val;
    g_xh[idx] = __float2half_rn(val);
}

// ---------------------------------------------------------------------------
// 2x2 attention per (sequence, head). One warp per (n,h).
// ---------------------------------------------------------------------------
template <bool L1>
__global__ void attn2(const __half* __restrict__ qkv,
                      const __half* __restrict__ qkv_p,
                      const float* __restrict__ peq,
                      const float* __restrict__ pek)
{
    int gw   = (blockIdx.x * blockDim.x + threadIdx.x) >> 5;
    int lane = threadIdx.x & 31;
    if (gw >= NSEQ * Hm) return;
    int n = gw / Hm;
    int h = gw - n * Hm;

    const int pidx = h * 64 + 2 * lane;
    size_t b0, b1;
    const __half* src0;
    if (L1) {
        src0 = qkv_p;
        b0 = (size_t)(n >> 6) * QKV + pidx;
        b1 = (size_t)(n ^ 1) * QKV + pidx;
    } else {
        src0 = qkv;
        b0 = (size_t)(2 * n) * QKV + pidx;
        b1 = b0 + QKV;
    }
    const int r1 = 1 + (n & 1);

    float2 hq0 = __half22float2(*(const __half2*)(src0 + b0));
    float2 hk0 = __half22float2(*(const __half2*)(src0 + b0 + Dm));
    float2 v0  = __half22float2(*(const __half2*)(src0 + b0 + 2 * Dm));
    float2 hq1 = __half22float2(*(const __half2*)(qkv + b1));
    float2 hk1 = __half22float2(*(const __half2*)(qkv + b1 + Dm));
    float2 v1  = __half22float2(*(const __half2*)(qkv + b1 + 2 * Dm));

    float2 pq0 = *(const float2*)(peq + pidx);
    float2 pk0 = *(const float2*)(pek + pidx);
    float2 pq1 = *(const float2*)(peq + r1 * Dm + pidx);
    float2 pk1 = *(const float2*)(pek + r1 * Dm + pidx);

    float2 q0 = make_float2(hq0.x + pq0.x, hq0.y + pq0.y);
    float2 k0 = make_float2(hk0.x + pk0.x, hk0.y + pk0.y);
    float2 q1 = make_float2(hq1.x + pq1.x, hq1.y + pq1.y);
    float2 k1 = make_float2(hk1.x + pk1.x, hk1.y + pk1.y);

    float s00 = q0.x * k0.x + q0.y * k0.y;
    float s01 = q0.x * k1.x + q0.y * k1.y;
    float s10 = q1.x * k0.x + q1.y * k0.y;
    float s11 = q1.x * k1.x + q1.y * k1.y;
#pragma unroll
    for (int o = 16; o; o >>= 1) {
        s00 += __shfl_xor_sync(0xffffffffu, s00, o);
        s01 += __shfl_xor_sync(0xffffffffu, s01, o);
        s10 += __shfl_xor_sync(0xffffffffu, s10, o);
        s11 += __shfl_xor_sync(0xffffffffu, s11, o);
    }
    const float sc = 0.125f;
    s00 *= sc; s01 *= sc; s10 *= sc; s11 *= sc;

    float m0 = fmaxf(s00, s01), m1 = fmaxf(s10, s11);
    float e00 = __expf(s00 - m0), e01 = __expf(s01 - m0);
    float e10 = __expf(s10 - m1), e11 = __expf(s11 - m1);
    float r0 = 1.f / (e00 + e01), rr1 = 1.f / (e10 + e11);
    float a00 = e00 * r0, a01 = e01 * r0;
    float a10 = e10 * rr1, a11 = e11 * rr1;

    size_t vbase = (size_t)(2 * n) * Dm + pidx;
    *(__half2*)(g_ah + vbase) =
        __floats2half2_rn(a00 * v0.x + a01 * v1.x, a00 * v0.y + a01 * v1.y);
    *(__half2*)(g_ah + vbase + Dm) =
        __floats2half2_rn(a10 * v0.x + a11 * v1.x, a10 * v0.y + a11 * v1.y);
}

// ---------------------------------------------------------------------------
// Warp-reduce helper
// ---------------------------------------------------------------------------
__device__ __forceinline__ float wsum(float v) {
#pragma unroll
    for (int o = 16; o; o >>= 1) v += __shfl_xor_sync(0xffffffffu, v, o);
    return v;
}

// x = inorm(x + delta): one warp per row; delta fp16; optional half-copy write
template <bool WRITEH>
__global__ void add_inorm(float* __restrict__ x, __half* __restrict__ xh,
                          const __half* __restrict__ delta)
{
    int row  = (blockIdx.x * blockDim.x + threadIdx.x) >> 5;
    int lane = threadIdx.x & 31;
    if (row >= TT) return;
    size_t base = (size_t)row * Dm;
    const float4*  xp = (const float4*)(x + base);
    const __half2* dp = (const __half2*)(delta + base);

    float4 v[6];
    float s = 0.f;
#pragma unroll
    for (int i = 0; i < 6; i++) {
        float4 a  = xp[lane + 32 * i];
        float2 d0 = __half22float2(dp[(lane + 32 * i) * 2]);
        float2 d1 = __half22float2(dp[(lane + 32 * i) * 2 + 1]);
        v[i].x = a.x + d0.x; v[i].y = a.y + d0.y;
        v[i].z = a.z + d1.x; v[i].w = a.w + d1.y;
        s += v[i].x + v[i].y + v[i].z + v[i].w;
    }
    float mean = wsum(s) * (1.f / 768.f);
    float vs = 0.f;
#pragma unroll
    for (int i = 0; i < 6; i++) {
        float dx = v[i].x - mean, dy = v[i].y - mean;
        float dz = v[i].z - mean, dw = v[i].w - mean;
        vs += dx * dx + dy * dy + dz * dz + dw * dw;
    }
    float rs = rsqrtf(wsum(vs) * (1.f / 768.f) + EPSf);

    float4*  xo = (float4*)(x + base);
    __half2* ho = (__half2*)(xh + base);
#pragma unroll
    for (int i = 0; i < 6; i++) {
        float4 r;
        r.x = (v[i].x - mean) * rs; r.y = (v[i].y - mean) * rs;
        r.z = (v[i].z - mean) * rs; r.w = (v[i].w - mean) * rs;
        xo[lane + 32 * i] = r;
        if (WRITEH) {
            ho[(lane + 32 * i) * 2]     = __floats2half2_rn(r.x, r.y);
            ho[(lane + 32 * i) * 2 + 1] = __floats2half2_rn(r.z, r.w);
        }
    }
}

// out_e[n] = inorm(x[2n] + x[2n+1]): one warp per sequence
__global__ void final_out(float* __restrict__ out)
{
    int n    = (blockIdx.x * blockDim.x + threadIdx.x) >> 5;
    int lane = threadIdx.x & 31;
    if (n >= NSEQ) return;
    size_t base = (size_t)(2 * n) * Dm;
    const float4* x0 = (const float4*)(g_x + base);
    const float4* x1 = (const float4*)(g_x + base + Dm);

    float4 v[6];
    float s = 0.f;
#pragma unroll
    for (int i = 0; i < 6; i++) {
        float4 a = x0[lane + 32 * i];
        float4 b = x1[lane + 32 * i];
        v[i].x = a.x + b.x; v[i].y = a.y + b.y;
        v[i].z = a.z + b.z; v[i].w = a.w + b.w;
        s += v[i].x + v[i].y + v[i].z + v[i].w;
    }
    float mean = wsum(s) * (1.f / 768.f);
    float vs = 0.f;
#pragma unroll
    for (int i = 0; i < 6; i++) {
        float dx = v[i].x - mean, dy = v[i].y - mean;
        float dz = v[i].z - mean, dw = v[i].w - mean;
        vs += dx * dx + dy * dy + dz * dz + dw * dw;
    }
    float rs = rsqrtf(wsum(vs) * (1.f / 768.f) + EPSf);

    float4* o = (float4*)(out + (size_t)n * Dm);
#pragma unroll
    for (int i = 0; i < 6; i++) {
        float4 r;
        r.x = (v[i].x - mean) * rs; r.y = (v[i].y - mean) * rs;
        r.z = (v[i].z - mean) * rs; r.w = (v[i].w - mean) * rs;
        o[lane + 32 * i] = r;
    }
}

// scores from half pc/lc/rc
__global__ void dot_scores(const __half* __restrict__ pc,
                           const __half* __restrict__ lc,
                           const __half* __restrict__ rc,
                           float* __restrict__ out)
{
    int gw   = (blockIdx.x * blockDim.x + threadIdx.x) >> 5;
    int lane = threadIdx.x & 31;
    if (gw >= NSEQ) return;
    int i     = gw >> 1;
    int which = gw & 1;
    int b     = i >> 5;
    const __half2* u = (const __half2*)(pc + (size_t)b * CSm);
    const __half2* w = (const __half2*)((which == 0 ? rc : lc) + (size_t)i * CSm);
    float s = 0.f;
#pragma unroll 4
    for (int j = lane; j < CSm / 2; j += 32) {
        float2 a = __half22float2(u[j]);
        float2 c = __half22float2(w[j]);
        s += a.x * c.x + a.y * c.y;
    }
    s = wsum(s);
    if (lane == 0) out[gw] = s * 0.044194173824159216f;
}

// ---------------------------------------------------------------------------
// Host launcher
// ---------------------------------------------------------------------------
static void* devptr(const void* sym)
{
    void* p = nullptr;
    cudaGetSymbolAddress(&p, sym);
    return p;
}

extern "C" void kernel_launch(void* const* d_in, const int* in_sizes, int n_in,
                              void* d_out, int out_size)
{
    (void)in_sizes; (void)n_in; (void)out_size;

    const float* parent     = (const float*)d_in[0];
    const float* child      = (const float*)d_in[1];
    const float* attn_in_w  = (const float*)d_in[4];
    const float* attn_in_b  = (const float*)d_in[5];
    const float* attn_out_w = (const float*)d_in[6];
    const float* attn_out_b = (const float*)d_in[7];
    const float* lin1_w     = (const float*)d_in[8];
    const float* lin1_b     = (const float*)d_in[9];
    const float* lin2_w     = (const float*)d_in[10];
    const float* lin2_b     = (const float*)d_in[11];
    const float* pos_emb    = (const float*)d_in[12];
    const float* parent_w1  = (const float*)d_in[13];
    const float* parent_b1  = (const float*)d_in[14];
    const float* parent_w2  = (const float*)d_in[15];
    const float* parent_b2  = (const float*)d_in[16];
    const float* left_w1    = (const float*)d_in[17];
    const float* left_b1    = (const float*)d_in[18];
    const float* left_w2    = (const float*)d_in[19];
    const float* left_b2    = (const float*)d_in[20];
    const float* right_w1   = (const float*)d_in[21];
    const float* right_b1   = (const float*)d_in[22];
    const float* right_w2   = (const float*)d_in[23];
    const float* right_b2   = (const float*)d_in[24];
    float* out = (float*)d_out;

    float*  px   = (float*) devptr(g_x);
    float*  ppeq = (float*) devptr(g_peq);
    float*  ppek = (float*) devptr(g_pek);
    __half* psc  = (__half*)devptr(g_sc);
    __half* pqkv = (__half*)devptr(g_qkvh);
    __half* pxh  = (__half*)devptr(g_xh);
    __half* pah  = (__half*)devptr(g_ah);
    __half* psh  = (__half*)devptr(g_sh);
    __half* phid = (__half*)devptr(g_hidh);
    __half* pwh  = (__half*)devptr(g_wh);
    __half* pch  = (__half*)devptr(g_ch);
    __half* pph  = (__half*)devptr(g_ph);

    constexpr int SMEMB = 3 * (128 + 128) * PS * 2;   // 110592 B -> 2 CTAs/SM
    static int attr_done = 0;
    static cudaStream_t s2 = nullptr;
    static cudaEvent_t evFork = nullptr, evJoin = nullptr;
    if (!attr_done) {
        cudaFuncSetAttribute(hgemm<false, true>,
                             cudaFuncAttributeMaxDynamicSharedMemorySize, SMEMB);
        cudaFuncSetAttribute(hgemm<true, true>,
                             cudaFuncAttributeMaxDynamicSharedMemorySize, SMEMB);
        cudaFuncSetAttribute(hgemm_b3<true, true>,
                             cudaFuncAttributeMaxDynamicSharedMemorySize, SMEMB);
        cudaFuncSetAttribute(hgemm_b3<false, true>,
                             cudaFuncAttributeMaxDynamicSharedMemorySize, SMEMB);
        cudaStreamCreateWithFlags(&s2, cudaStreamNonBlocking);
        cudaEventCreateWithFlags(&evFork, cudaEventDisableTiming);
        cudaEventCreateWithFlags(&evJoin, cudaEventDisableTiming);
        attr_done = 1;
    }

    // ---- fp16 conversion layout (offsets into g_wh) ----
    const int n_aiw = Lm * 3 * Dm * Dm;
    const int n_aow = Lm * Dm * Dm;
    const int n_l1  = Lm * FFm * Dm;
    const int n_l2  = Lm * Dm * FFm;
    const int n_w1  = Dm * Dm;
    const int n_w2  = CSm * Dm;

    __half* w_aiw = pwh;
    __half* w_aow = w_aiw + n_aiw;
    __half* w_l1  = w_aow + n_aow;
    __half* w_l2  = w_l1  + n_l1;
    __half* w_pw1 = w_l2  + n_l2;
    __half* w_pw2 = w_pw1 + n_w1;
    __half* w_lw1 = w_pw2 + n_w2;
    __half* w_lw2 = w_lw1 + n_w1;
    __half* w_rw1 = w_lw2 + n_w2;
    __half* w_rw2 = w_rw1 + n_w1;

    // single fused conversion launch
    {
        struct S { const float* s; __half* d; int n; };
        S segs[12] = {
            {attn_in_w,  w_aiw, n_aiw}, {attn_out_w, w_aow, n_aow},
            {lin1_w,     w_l1,  n_l1},  {lin2_w,     w_l2,  n_l2},
            {parent_w1,  w_pw1, n_w1},  {parent_w2,  w_pw2, n_w2},
            {left_w1,    w_lw1, n_w1},  {left_w2,    w_lw2, n_w2},
            {right_w1,   w_rw1, n_w1},  {right_w2,   w_rw2, n_w2},
            {child,      pch,   NSEQ * Dm}, {parent, pph,   Bm * Dm},
        };
        CvtArgs ca;
        int acc = 0;
        for (int i = 0; i < 12; i++) {
            ca.src[i] = (const float2*)segs[i].s;
            ca.dst[i] = (__half2*)segs[i].d;
            acc += segs[i].n / 2;
            ca.end[i] = acc;
        }
        cvt_all<<<(acc + 255) / 256, 256>>>(ca, acc);
    }

    // pe @ W{q,k}^T biases
    peb<<<(2 * Lm * 3 * Dm * 32) / 256, 256>>>(pos_emb, w_aiw, ppeq, ppek);

    const int EW = (TT * Dm) / 256;
    build_x<<<EW, 256>>>(parent, child);

    // ---- fork: score path runs concurrently on s2 (independent buffers) ----
    cudaEventRecord(evFork, 0);
    cudaStreamWaitEvent(s2, evFork, 0);
    {
        __half* h_lft = psh;                              // 8192 x 768
        __half* h_rgt = psh + (size_t)8192 * Dm;
        __half* h_par = psh + (size_t)16384 * Dm;         // 256 x 768
        __half* o_lc  = psc;                              // 8192 x 512 (half)
        __half* o_rc  = psc + (size_t)8192 * CSm;
        __half* o_pc  = psc + (size_t)16384 * CSm;        // 256 x 512

        hgemm_b3<true, true><<<dim3(6, 130), NTHR, SMEMB, s2>>>(
            pch,      2 * Dm, w_lw1, left_b1,   h_lft,
            pch + Dm, 2 * Dm, w_rw1, right_b1,  h_rgt,
            pph,      Dm,     w_pw1, parent_b1, h_par,
            64, 128, Dm, Dm);
        hgemm_b3<false, true><<<dim3(4, 130), NTHR, SMEMB, s2>>>(
            h_lft, Dm, w_lw2, left_b2,   o_lc,
            h_rgt, Dm, w_rw2, right_b2,  o_rc,
            h_par, Dm, w_pw2, parent_b2, o_pc,
            64, 128, CSm, Dm);
        dot_scores<<<(NSEQ * 32) / 256, 256, 0, s2>>>(o_pc, o_lc, o_rc, out);
        cudaEventRecord(evJoin, s2);
    }

    // ---- 3 tree-transformer layers (main stream) ----
    dim3 gQKV(QKV / 128, TT / 128);    // (18, 256)
    dim3 gD  (Dm  / 128, TT / 128);    // (6, 256)
    dim3 gM1 (FFm / 128, TT / 128);    // (24, 256)
    __half* pqkv_p = pqkv + (size_t)NSEQ * QKV;   // parent QKV (layer 1)
    __half* pdh    = pqkv;                        // half delta (reuse after attn2)

    for (int l = 0; l < Lm; l++) {
        const __half* iw = w_aiw + (size_t)l * 3 * Dm * Dm;
        const float*  ib = attn_in_b  + (size_t)l * 3 * Dm;
        const __half* ow = w_aow + (size_t)l * Dm * Dm;
        const float*  ob = attn_out_b + (size_t)l * Dm;
        const __half* w1 = w_l1  + (size_t)l * FFm * Dm;
        const float*  b1 = lin1_b     + (size_t)l * FFm;
        const __half* w2 = w_l2  + (size_t)l * Dm * FFm;
        const float*  b2 = lin2_b     + (size_t)l * Dm;

        if (l == 0) {
            hgemm_b3<false, true><<<dim3(QKV / 128, 130), NTHR, SMEMB>>>(
                pch, Dm, iw, ib, pqkv,
                pph, Dm, iw, ib, pqkv_p,
                pph, Dm, iw, ib, pqkv_p,      // unused segment
                128, 130, QKV, Dm);
            attn2<true><<<(NSEQ * Hm * 32) / 256, 256>>>(pqkv, pqkv_p, ppeq, ppek);
        } else {
            hgemm<false, true><<<gQKV, NTHR, SMEMB>>>(pxh, Dm, iw, ib, pqkv, QKV, Dm);
            attn2<false><<<(NSEQ * Hm * 32) / 256, 256>>>(
                pqkv, pqkv,
                ppeq + (size_t)l * 3 * Dm, ppek + (size_t)l * 3 * Dm);
        }
        // out-proj -> half delta, then x = inorm(x + delta)
        hgemm<false, true><<<gD , NTHR, SMEMB>>>(pah, Dm, ow, ob, pdh, Dm, Dm);
        add_inorm<true><<<(TT * 32) / 256, 256>>>(px, pxh, pdh);
        // MLP
        hgemm<true , true><<<gM1, NTHR, SMEMB>>>(pxh,  Dm,  w1, b1, phid, FFm, Dm);
        hgemm<false, true><<<gD , NTHR, SMEMB>>>(phid, FFm, w2, b2, pdh,  Dm,  FFm);
        if (l + 1 < Lm)
            add_inorm<true ><<<(TT * 32) / 256, 256>>>(px, pxh, pdh);
        else
            add_inorm<false><<<(TT * 32) / 256, 256>>>(px, pxh, pdh);
    }

    // ---- join score path, then final output ----
    cudaStreamWaitEvent(0, evJoin, 0);
    final_out<<<(NSEQ * 32) / 256, 256>>>(out + NSEQ);
}

// round 15
// speedup vs baseline: 1.0351x; 1.0351x over previous
#include <cuda_runtime.h>
#include <cuda_fp16.h>
#include <math.h>
#include <stdint.h>

// ---------------------------------------------------------------------------
// Problem constants
// ---------------------------------------------------------------------------
namespace {
constexpr int Dm   = 768;
constexpr int FFm  = 3072;
constexpr int Hm   = 12;
constexpr int Lm   = 3;
constexpr int CSm  = 512;
constexpr int Bm   = 256;
constexpr int NSEQ = 16384;         // sequences of 2 tokens
constexpr int TT   = NSEQ * 2;      // 32768 tokens
constexpr float EPSf = 1e-5f;
constexpr int PS   = 72;            // smem row stride in halves (BK=64 + 8 pad)
constexpr int QKV  = 2304;          // fused QKV width
constexpr int NTHR = 256;           // gemm block size (8 warps) — R13 optimum
}

// ---------------------------------------------------------------------------
// Scratch (device globals; no runtime allocation allowed)
// ---------------------------------------------------------------------------
__device__ float g_x [TT * Dm];                    // fp32 residual state
__device__ float g_peq[Lm * 3 * Dm];               // pe @ Wq^T per (layer,role)
__device__ float g_pek[Lm * 3 * Dm];               // pe @ Wk^T per (layer,role)
__device__ __align__(16) __half g_sc  [TT * CSm];  // score outs (half)
__device__ __align__(16) __half g_qkvh[TT * QKV];  // fused QKV / half delta
__device__ __align__(16) __half g_xh  [TT * Dm];   // half copy of x
__device__ __align__(16) __half g_ah  [TT * Dm];   // attn-out
__device__ __align__(16) __half g_sh  [16640 * Dm];// score-path hiddens (own buf)
__device__ __align__(16) __half g_hidh[TT * FFm];  // MLP hidden (half)
__device__ __align__(16) __half g_wh  [24182784];  // all weights, half
__device__ __align__(16) __half g_ch  [TT * Dm];   // child, half
__device__ __align__(16) __half g_ph  [Bm * Dm];   // parent, half

__device__ __forceinline__ float gelu_f(float x) {
    return 0.5f * x * (1.0f + erff(x * 0.7071067811865475f));
}

__device__ __forceinline__ void cp_async16(uint32_t s, const void* g) {
    asm volatile("cp.async.cg.shared.global [%0], [%1], 16;\n" :: "r"(s), "l"(g));
}
__device__ __forceinline__ void cp_commit() {
    asm volatile("cp.async.commit_group;\n");
}
template <int N> __device__ __forceinline__ void cp_wait() {
    asm volatile("cp.async.wait_group %0;\n" :: "n"(N));
}
__device__ __forceinline__ void ldsm4(uint32_t& r0, uint32_t& r1,
                                      uint32_t& r2, uint32_t& r3, uint32_t addr) {
    asm volatile("ldmatrix.sync.aligned.m8n8.x4.shared.b16 {%0,%1,%2,%3}, [%4];"
                 : "=r"(r0), "=r"(r1), "=r"(r2), "=r"(r3) : "r"(addr));
}
__device__ __forceinline__ void mma16816(float* c, const uint32_t* a, const uint32_t* b) {
    asm volatile(
        "mma.sync.aligned.m16n8k16.row.col.f32.f16.f16.f32 "
        "{%0,%1,%2,%3}, {%4,%5,%6,%7}, {%8,%9}, {%0,%1,%2,%3};"
        : "+f"(c[0]), "+f"(c[1]), "+f"(c[2]), "+f"(c[3])
        : "r"(a[0]), "r"(a[1]), "r"(a[2]), "r"(a[3]), "r"(b[0]), "r"(b[1]));
}

// ---------------------------------------------------------------------------
// GEMM body: CTA 128x128, 8 warps (2m x 4n), warp tile 64x32, BK=64,
// m16n8k16 HMMA + ldmatrix.x4, 3-stage cp.async pipeline, 2 CTAs/SM.
// R13 optimum: 40.6% tensor against ~40% crossbar ceiling. DO NOT TOUCH.
// ---------------------------------------------------------------------------
template <bool GELU, bool HALFOUT>
__device__ __forceinline__ void gemm_body(
    const __half* __restrict__ A, int lda,
    const __half* __restrict__ B, const float* __restrict__ bias,
    void* __restrict__ Cv, int ldc, int K, int bm, int bn, __half* sh)
{
    constexpr int BM = 128, BN = 128, BK = 64, ST = 3;
    constexpr int ASZ = BM * PS;
    constexpr int BSZ = BN * PS;
    __half* As = sh;
    __half* Bs = sh + ST * ASZ;

    const int tid  = threadIdx.x;
    const int lane = tid & 31;
    const int wid  = tid >> 5;
    const int wm   = wid >> 2;
    const int wn   = wid & 3;

    const int r0 = tid >> 3;
    const int cc = (tid & 7) * 8;
    const __half* Ap = A + (size_t)(bm + r0) * lda + cc;
    const __half* Bp = B + (size_t)(bn + r0) * K   + cc;

    const uint32_t sAbase = (uint32_t)__cvta_generic_to_shared(As);
    const uint32_t sBbase = (uint32_t)__cvta_generic_to_shared(Bs);
    const uint32_t sA = sAbase + (r0 * PS + cc) * 2;
    const uint32_t sB = sBbase + (r0 * PS + cc) * 2;

    const int nk = K / BK;

    auto issue = [&](int st, int kt) {
        const __half* Ag = Ap + kt * BK;
        const __half* Bg = Bp + kt * BK;
        uint32_t a = sA + st * (ASZ * 2);
        uint32_t b = sB + st * (BSZ * 2);
#pragma unroll
        for (int i = 0; i < 4; i++)
            cp_async16(a + i * 32 * PS * 2, Ag + (size_t)i * 32 * lda);
#pragma unroll
        for (int i = 0; i < 4; i++)
            cp_async16(b + i * 32 * PS * 2, Bg + (size_t)i * 32 * K);
        cp_commit();
    };

    float c[4][4][4];
#pragma unroll
    for (int mt = 0; mt < 4; mt++)
#pragma unroll
        for (int nt = 0; nt < 4; nt++)
#pragma unroll
            for (int j = 0; j < 4; j++) c[mt][nt][j] = 0.f;

    const int aOff = (wm * 64 + (lane & 15)) * PS + (lane >> 4) * 8;
    const int bOff = (wn * 32 + (lane & 7) + ((lane >> 4) & 1) * 8) * PS
                   + ((lane >> 3) & 1) * 8;

    issue(0, 0);
    issue(1, 1);

    for (int it = 0; it < nk; it++) {
        cp_wait<1>();
        __syncthreads();
        if (it + 2 < nk) issue((it + 2) % 3, it + 2);
        else             cp_commit();

        const int st = it % 3;
        const uint32_t aS = sAbase + (st * ASZ) * 2;
        const uint32_t bS = sBbase + (st * BSZ) * 2;
#pragma unroll
        for (int ks = 0; ks < 4; ks++) {
            uint32_t a[4][4], b[4][2];
#pragma unroll
            for (int mt = 0; mt < 4; mt++)
                ldsm4(a[mt][0], a[mt][1], a[mt][2], a[mt][3],
                      aS + (aOff + mt * 16 * PS + ks * 16) * 2);
#pragma unroll
            for (int np = 0; np < 2; np++)
                ldsm4(b[2 * np][0], b[2 * np][1], b[2 * np + 1][0], b[2 * np + 1][1],
                      bS + (bOff + np * 16 * PS + ks * 16) * 2);
#pragma unroll
            for (int mt = 0; mt < 4; mt++)
#pragma unroll
                for (int nt = 0; nt < 4; nt++)
                    mma16816(c[mt][nt], a[mt], b[nt]);
        }
    }

    const int g  = lane >> 2;
    const int tg = lane & 3;
#pragma unroll
    for (int mt = 0; mt < 4; mt++) {
        const int row = bm + wm * 64 + mt * 16 + g;
#pragma unroll
        for (int nt = 0; nt < 4; nt++) {
            const int col = bn + wn * 32 + nt * 8 + 2 * tg;
            const float bx = bias[col], by = bias[col + 1];
            float v0x = c[mt][nt][0] + bx, v0y = c[mt][nt][1] + by;
            float v1x = c[mt][nt][2] + bx, v1y = c[mt][nt][3] + by;
            if (GELU) {
                v0x = gelu_f(v0x); v0y = gelu_f(v0y);
                v1x = gelu_f(v1x); v1y = gelu_f(v1y);
            }
            if (HALFOUT) {
                __half* C = (__half*)Cv;
                *(__half2*)(C + (size_t)row * ldc + col)       = __floats2half2_rn(v0x, v0y);
                *(__half2*)(C + (size_t)(row + 8) * ldc + col) = __floats2half2_rn(v1x, v1y);
            } else {
                float* C = (float*)Cv;
                *(float2*)(C + (size_t)row * ldc + col)       = make_float2(v0x, v0y);
                *(float2*)(C + (size_t)(row + 8) * ldc + col) = make_float2(v1x, v1y);
            }
        }
    }
}

template <bool GELU, bool HALFOUT>
__global__ void __launch_bounds__(NTHR, 2) hgemm(
    const __half* __restrict__ A, int lda,
    const __half* __restrict__ B, const float* __restrict__ bias,
    void* __restrict__ Cv, int ldc, int K)
{
    extern __shared__ __half sh[];
    gemm_body<GELU, HALFOUT>(A, lda, B, bias, Cv, ldc, K,
                             blockIdx.y * 128, blockIdx.x * 128, sh);
}

// 3-segment batched GEMM: blockIdx.y range selects (A,lda,B,bias,C)
template <bool GELU, bool HALFOUT>
__global__ void __launch_bounds__(NTHR, 2) hgemm_b3(
    const __half* A0, int lda0, const __half* B0, const float* bias0, void* C0,
    const __half* A1, int lda1, const __half* B1, const float* bias1, void* C1,
    const __half* A2, int lda2, const __half* B2, const float* bias2, void* C2,
    int y1, int y2, int ldc, int K)
{
    extern __shared__ __half sh[];
    const int y = blockIdx.y;
    const __half* A; int lda; const __half* B; const float* bias; void* C; int ly;
    if (y < y1)      { A = A0; lda = lda0; B = B0; bias = bias0; C = C0; ly = y; }
    else if (y < y2) { A = A1; lda = lda1; B = B1; bias = bias1; C = C1; ly = y - y1; }
    else             { A = A2; lda = lda2; B = B2; bias = bias2; C = C2; ly = y - y2; }
    gemm_body<GELU, HALFOUT>(A, lda, B, bias, C, ldc, K,
                             ly * 128, blockIdx.x * 128, sh);
}

// ---------------------------------------------------------------------------
// Fused fp32 -> fp16 conversion for all segments (single launch)
// ---------------------------------------------------------------------------
struct CvtArgs {
    const float2* src[12];
    __half2*      dst[12];
    int           end[12];
};
__global__ void cvt_all(CvtArgs a, int total2)
{
    int i = blockIdx.x * blockDim.x + threadIdx.x;
    if (i >= total2) return;
    int s = 0;
#pragma unroll
    for (int k = 0; k < 11; k++) s += (i >= a.end[s]) ? 1 : 0;
    int base = s ? a.end[s - 1] : 0;
    float2 v = a.src[s][i - base];
    a.dst[s][i - base] = __floats2half2_rn(v.x, v.y);
}

// ---------------------------------------------------------------------------
// pe-projection biases
// ---------------------------------------------------------------------------
__global__ void peb(const float* __restrict__ pos_emb,
                    const __half* __restrict__ w_aiw,
                    float* __restrict__ peq, float* __restrict__ pek)
{
    int gw   = (blockIdx.x * blockDim.x + threadIdx.x) >> 5;
    int lane = threadIdx.x & 31;
    if (gw >= 2 * Lm * 3 * Dm) return;
    int d  = gw % Dm;
    int t  = gw / Dm;
    int r  = t % 3;
    int qk = (t / 3) % 2;
    int l  = t / 6;

    const __half* wrow = w_aiw + ((size_t)l * 3 * Dm + qk * Dm + d) * Dm;
    const float*  pe   = pos_emb + (size_t)(l * 4 + r) * Dm;
    float s = 0.f;
#pragma unroll 4
    for (int j = lane; j < Dm; j += 32) s += pe[j] * __half2float(wrow[j]);
#pragma unroll
    for (int o = 16; o; o >>= 1) s += __shfl_xor_sync(0xffffffffu, s, o);
    if (lane == 0)
        (qk ? pek : peq)[(l * 3 + r) * Dm + d] = s;
}

// ---------------------------------------------------------------------------
// 2x2 attention per (sequence, head). One warp per (n,h).
// ---------------------------------------------------------------------------
template <bool L1>
__global__ void attn2(const __half* __restrict__ qkv,
                      const __half* __restrict__ qkv_p,
                      const float* __restrict__ peq,
                      const float* __restrict__ pek)
{
    int gw   = (blockIdx.x * blockDim.x + threadIdx.x) >> 5;
    int lane = threadIdx.x & 31;
    if (gw >= NSEQ * Hm) return;
    int n = gw / Hm;
    int h = gw - n * Hm;

    const int pidx = h * 64 + 2 * lane;
    size_t b0, b1;
    const __half* src0;
    if (L1) {
        src0 = qkv_p;
        b0 = (size_t)(n >> 6) * QKV + pidx;
        b1 = (size_t)(n ^ 1) * QKV + pidx;
    } else {
        src0 = qkv;
        b0 = (size_t)(2 * n) * QKV + pidx;
        b1 = b0 + QKV;
    }
    const int r1 = 1 + (n & 1);

    float2 hq0 = __half22float2(*(const __half2*)(src0 + b0));
    float2 hk0 = __half22float2(*(const __half2*)(src0 + b0 + Dm));
    float2 v0  = __half22float2(*(const __half2*)(src0 + b0 + 2 * Dm));
    float2 hq1 = __half22float2(*(const __half2*)(qkv + b1));
    float2 hk1 = __half22float2(*(const __half2*)(qkv + b1 + Dm));
    float2 v1  = __half22float2(*(const __half2*)(qkv + b1 + 2 * Dm));

    float2 pq0 = *(const float2*)(peq + pidx);
    float2 pk0 = *(const float2*)(pek + pidx);
    float2 pq1 = *(const float2*)(peq + r1 * Dm + pidx);
    float2 pk1 = *(const float2*)(pek + r1 * Dm + pidx);

    float2 q0 = make_float2(hq0.x + pq0.x, hq0.y + pq0.y);
    float2 k0 = make_float2(hk0.x + pk0.x, hk0.y + pk0.y);
    float2 q1 = make_float2(hq1.x + pq1.x, hq1.y + pq1.y);
    float2 k1 = make_float2(hk1.x + pk1.x, hk1.y + pk1.y);

    float s00 = q0.x * k0.x + q0.y * k0.y;
    float s01 = q0.x * k1.x + q0.y * k1.y;
    float s10 = q1.x * k0.x + q1.y * k0.y;
    float s11 = q1.x * k1.x + q1.y * k1.y;
#pragma unroll
    for (int o = 16; o; o >>= 1) {
        s00 += __shfl_xor_sync(0xffffffffu, s00, o);
        s01 += __shfl_xor_sync(0xffffffffu, s01, o);
        s10 += __shfl_xor_sync(0xffffffffu, s10, o);
        s11 += __shfl_xor_sync(0xffffffffu, s11, o);
    }
    const float sc = 0.125f;
    s00 *= sc; s01 *= sc; s10 *= sc; s11 *= sc;

    float m0 = fmaxf(s00, s01), m1 = fmaxf(s10, s11);
    float e00 = __expf(s00 - m0), e01 = __expf(s01 - m0);
    float e10 = __expf(s10 - m1), e11 = __expf(s11 - m1);
    float r0 = 1.f / (e00 + e01), rr1 = 1.f / (e10 + e11);
    float a00 = e00 * r0, a01 = e01 * r0;
    float a10 = e10 * rr1, a11 = e11 * rr1;

    size_t vbase = (size_t)(2 * n) * Dm + pidx;
    *(__half2*)(g_ah + vbase) =
        __floats2half2_rn(a00 * v0.x + a01 * v1.x, a00 * v0.y + a01 * v1.y);
    *(__half2*)(g_ah + vbase + Dm) =
        __floats2half2_rn(a10 * v0.x + a11 * v1.x, a10 * v0.y + a11 * v1.y);
}

// ---------------------------------------------------------------------------
// Warp-reduce helper
// ---------------------------------------------------------------------------
__device__ __forceinline__ float wsum(float v) {
#pragma unroll
    for (int o = 16; o; o >>= 1) v += __shfl_xor_sync(0xffffffffu, v, o);
    return v;
}

// x = inorm(x_src + delta): one warp per row; delta fp16.
// FIRST: gather x_src directly from parent/child (build_x eliminated).
// WRITEH: also write the fp16 copy of the result.
template <bool FIRST, bool WRITEH>
__global__ void add_inorm(float* __restrict__ x, __half* __restrict__ xh,
                          const __half* __restrict__ delta,
                          const float* __restrict__ parent,
                          const float* __restrict__ child)
{
    int row  = (blockIdx.x * blockDim.x + threadIdx.x) >> 5;
    int lane = threadIdx.x & 31;
    if (row >= TT) return;
    size_t base = (size_t)row * Dm;

    const float4* xp;
    if (FIRST) {
        if ((row & 1) == 0)
            xp = (const float4*)(parent + (size_t)(row >> 7) * Dm);
        else
            xp = (const float4*)(child + (size_t)((row >> 1) ^ 1) * Dm);
    } else {
        xp = (const float4*)(x + base);
    }
    const __half2* dp = (const __half2*)(delta + base);

    float4 v[6];
    float s = 0.f;
#pragma unroll
    for (int i = 0; i < 6; i++) {
        float4 a  = xp[lane + 32 * i];
        float2 d0 = __half22float2(dp[(lane + 32 * i) * 2]);
        float2 d1 = __half22float2(dp[(lane + 32 * i) * 2 + 1]);
        v[i].x = a.x + d0.x; v[i].y = a.y + d0.y;
        v[i].z = a.z + d1.x; v[i].w = a.w + d1.y;
        s += v[i].x + v[i].y + v[i].z + v[i].w;
    }
    float mean = wsum(s) * (1.f / 768.f);
    float vs = 0.f;
#pragma unroll
    for (int i = 0; i < 6; i++) {
        float dx = v[i].x - mean, dy = v[i].y - mean;
        float dz = v[i].z - mean, dw = v[i].w - mean;
        vs += dx * dx + dy * dy + dz * dz + dw * dw;
    }
    float rs = rsqrtf(wsum(vs) * (1.f / 768.f) + EPSf);

    float4*  xo = (float4*)(x + base);
    __half2* ho = (__half2*)(xh + base);
#pragma unroll
    for (int i = 0; i < 6; i++) {
        float4 r;
        r.x = (v[i].x - mean) * rs; r.y = (v[i].y - mean) * rs;
        r.z = (v[i].z - mean) * rs; r.w = (v[i].w - mean) * rs;
        xo[lane + 32 * i] = r;
        if (WRITEH) {
            ho[(lane + 32 * i) * 2]     = __floats2half2_rn(r.x, r.y);
            ho[(lane + 32 * i) * 2 + 1] = __floats2half2_rn(r.z, r.w);
        }
    }
}

// out_e[n] = inorm(x[2n] + x[2n+1]): one warp per sequence
__global__ void final_out(float* __restrict__ out)
{
    int n    = (blockIdx.x * blockDim.x + threadIdx.x) >> 5;
    int lane = threadIdx.x & 31;
    if (n >= NSEQ) return;
    size_t base = (size_t)(2 * n) * Dm;
    const float4* x0 = (const float4*)(g_x + base);
    const float4* x1 = (const float4*)(g_x + base + Dm);

    float4 v[6];
    float s = 0.f;
#pragma unroll
    for (int i = 0; i < 6; i++) {
        float4 a = x0[lane + 32 * i];
        float4 b = x1[lane + 32 * i];
        v[i].x = a.x + b.x; v[i].y = a.y + b.y;
        v[i].z = a.z + b.z; v[i].w = a.w + b.w;
        s += v[i].x + v[i].y + v[i].z + v[i].w;
    }
    float mean = wsum(s) * (1.f / 768.f);
    float vs = 0.f;
#pragma unroll
    for (int i = 0; i < 6; i++) {
        float dx = v[i].x - mean, dy = v[i].y - mean;
        float dz = v[i].z - mean, dw = v[i].w - mean;
        vs += dx * dx + dy * dy + dz * dz + dw * dw;
    }
    float rs = rsqrtf(wsum(vs) * (1.f / 768.f) + EPSf);

    float4* o = (float4*)(out + (size_t)n * Dm);
#pragma unroll
    for (int i = 0; i < 6; i++) {
        float4 r;
        r.x = (v[i].x - mean) * rs; r.y = (v[i].y - mean) * rs;
        r.z = (v[i].z - mean) * rs; r.w = (v[i].w - mean) * rs;
        o[lane + 32 * i] = r;
    }
}

// scores from half pc/lc/rc
__global__ void dot_scores(const __half* __restrict__ pc,
                           const __half* __restrict__ lc,
                           const __half* __restrict__ rc,
                           float* __restrict__ out)
{
    int gw   = (blockIdx.x * blockDim.x + threadIdx.x) >> 5;
    int lane = threadIdx.x & 31;
    if (gw >= NSEQ) return;
    int i     = gw >> 1;
    int which = gw & 1;
    int b     = i >> 5;
    const __half2* u = (const __half2*)(pc + (size_t)b * CSm);
    const __half2* w = (const __half2*)((which == 0 ? rc : lc) + (size_t)i * CSm);
    float s = 0.f;
#pragma unroll 4
    for (int j = lane; j < CSm / 2; j += 32) {
        float2 a = __half22float2(u[j]);
        float2 c = __half22float2(w[j]);
        s += a.x * c.x + a.y * c.y;
    }
    s = wsum(s);
    if (lane == 0) out[gw] = s * 0.044194173824159216f;
}

// ---------------------------------------------------------------------------
// Host launcher
// ---------------------------------------------------------------------------
static void* devptr(const void* sym)
{
    void* p = nullptr;
    cudaGetSymbolAddress(&p, sym);
    return p;
}

extern "C" void kernel_launch(void* const* d_in, const int* in_sizes, int n_in,
                              void* d_out, int out_size)
{
    (void)in_sizes; (void)n_in; (void)out_size;

    const float* parent     = (const float*)d_in[0];
    const float* child      = (const float*)d_in[1];
    const float* attn_in_w  = (const float*)d_in[4];
    const float* attn_in_b  = (const float*)d_in[5];
    const float* attn_out_w = (const float*)d_in[6];
    const float* attn_out_b = (const float*)d_in[7];
    const float* lin1_w     = (const float*)d_in[8];
    const float* lin1_b     = (const float*)d_in[9];
    const float* lin2_w     = (const float*)d_in[10];
    const float* lin2_b     = (const float*)d_in[11];
    const float* pos_emb    = (const float*)d_in[12];
    const float* parent_w1  = (const float*)d_in[13];
    const float* parent_b1  = (const float*)d_in[14];
    const float* parent_w2  = (const float*)d_in[15];
    const float* parent_b2  = (const float*)d_in[16];
    const float* left_w1    = (const float*)d_in[17];
    const float* left_b1    = (const float*)d_in[18];
    const float* left_w2    = (const float*)d_in[19];
    const float* left_b2    = (const float*)d_in[20];
    const float* right_w1   = (const float*)d_in[21];
    const float* right_b1   = (const float*)d_in[22];
    const float* right_w2   = (const float*)d_in[23];
    const float* right_b2   = (const float*)d_in[24];
    float* out = (float*)d_out;

    float*  px   = (float*) devptr(g_x);
    float*  ppeq = (float*) devptr(g_peq);
    float*  ppek = (float*) devptr(g_pek);
    __half* psc  = (__half*)devptr(g_sc);
    __half* pqkv = (__half*)devptr(g_qkvh);
    __half* pxh  = (__half*)devptr(g_xh);
    __half* pah  = (__half*)devptr(g_ah);
    __half* psh  = (__half*)devptr(g_sh);
    __half* phid = (__half*)devptr(g_hidh);
    __half* pwh  = (__half*)devptr(g_wh);
    __half* pch  = (__half*)devptr(g_ch);
    __half* pph  = (__half*)devptr(g_ph);

    constexpr int SMEMB = 3 * (128 + 128) * PS * 2;   // 110592 B -> 2 CTAs/SM
    static int attr_done = 0;
    static cudaStream_t s2 = nullptr;
    static cudaEvent_t evFork = nullptr, evJoin = nullptr;
    if (!attr_done) {
        cudaFuncSetAttribute(hgemm<false, true>,
                             cudaFuncAttributeMaxDynamicSharedMemorySize, SMEMB);
        cudaFuncSetAttribute(hgemm<true, true>,
                             cudaFuncAttributeMaxDynamicSharedMemorySize, SMEMB);
        cudaFuncSetAttribute(hgemm_b3<true, true>,
                             cudaFuncAttributeMaxDynamicSharedMemorySize, SMEMB);
        cudaFuncSetAttribute(hgemm_b3<false, true>,
                             cudaFuncAttributeMaxDynamicSharedMemorySize, SMEMB);
        cudaStreamCreateWithFlags(&s2, cudaStreamNonBlocking);
        cudaEventCreateWithFlags(&evFork, cudaEventDisableTiming);
        cudaEventCreateWithFlags(&evJoin, cudaEventDisableTiming);
        attr_done = 1;
    }

    // ---- fp16 conversion layout (offsets into g_wh) ----
    const int n_aiw = Lm * 3 * Dm * Dm;
    const int n_aow = Lm * Dm * Dm;
    const int n_l1  = Lm * FFm * Dm;
    const int n_l2  = Lm * Dm * FFm;
    const int n_w1  = Dm * Dm;
    const int n_w2  = CSm * Dm;

    __half* w_aiw = pwh;
    __half* w_aow = w_aiw + n_aiw;
    __half* w_l1  = w_aow + n_aow;
    __half* w_l2  = w_l1  + n_l1;
    __half* w_pw1 = w_l2  + n_l2;
    __half* w_pw2 = w_pw1 + n_w1;
    __half* w_lw1 = w_pw2 + n_w2;
    __half* w_lw2 = w_lw1 + n_w1;
    __half* w_rw1 = w_lw2 + n_w2;
    __half* w_rw2 = w_rw1 + n_w1;

    // single fused conversion launch
    {
        struct S { const float* s; __half* d; int n; };
        S segs[12] = {
            {attn_in_w,  w_aiw, n_aiw}, {attn_out_w, w_aow, n_aow},
            {lin1_w,     w_l1,  n_l1},  {lin2_w,     w_l2,  n_l2},
            {parent_w1,  w_pw1, n_w1},  {parent_w2,  w_pw2, n_w2},
            {left_w1,    w_lw1, n_w1},  {left_w2,    w_lw2, n_w2},
            {right_w1,   w_rw1, n_w1},  {right_w2,   w_rw2, n_w2},
            {child,      pch,   NSEQ * Dm}, {parent, pph,   Bm * Dm},
        };
        CvtArgs ca;
        int acc = 0;
        for (int i = 0; i < 12; i++) {
            ca.src[i] = (const float2*)segs[i].s;
            ca.dst[i] = (__half2*)segs[i].d;
            acc += segs[i].n / 2;
            ca.end[i] = acc;
        }
        cvt_all<<<(acc + 255) / 256, 256>>>(ca, acc);
    }

    // pe @ W{q,k}^T biases
    peb<<<(2 * Lm * 3 * Dm * 32) / 256, 256>>>(pos_emb, w_aiw, ppeq, ppek);

    // ---- fork: score path runs concurrently on s2 (independent buffers) ----
    cudaEventRecord(evFork, 0);
    cudaStreamWaitEvent(s2, evFork, 0);
    {
        __half* h_lft = psh;                              // 8192 x 768
        __half* h_rgt = psh + (size_t)8192 * Dm;
        __half* h_par = psh + (size_t)16384 * Dm;         // 256 x 768
        __half* o_lc  = psc;                              // 8192 x 512 (half)
        __half* o_rc  = psc + (size_t)8192 * CSm;
        __half* o_pc  = psc + (size_t)16384 * CSm;        // 256 x 512

        hgemm_b3<true, true><<<dim3(6, 130), NTHR, SMEMB, s2>>>(
            pch,      2 * Dm, w_lw1, left_b1,   h_lft,
            pch + Dm, 2 * Dm, w_rw1, right_b1,  h_rgt,
            pph,      Dm,     w_pw1, parent_b1, h_par,
            64, 128, Dm, Dm);
        hgemm_b3<false, true><<<dim3(4, 130), NTHR, SMEMB, s2>>>(
            h_lft, Dm, w_lw2, left_b2,   o_lc,
            h_rgt, Dm, w_rw2, right_b2,  o_rc,
            h_par, Dm, w_pw2, parent_b2, o_pc,
            64, 128, CSm, Dm);
        dot_scores<<<(NSEQ * 32) / 256, 256, 0, s2>>>(o_pc, o_lc, o_rc, out);
        cudaEventRecord(evJoin, s2);
    }

    // ---- 3 tree-transformer layers (main stream) ----
    dim3 gQKV(QKV / 128, TT / 128);    // (18, 256)
    dim3 gD  (Dm  / 128, TT / 128);    // (6, 256)
    dim3 gM1 (FFm / 128, TT / 128);    // (24, 256)
    __half* pqkv_p = pqkv + (size_t)NSEQ * QKV;   // parent QKV (layer 1)
    __half* pdh    = pqkv;                        // half delta (reuse after attn2)
    const int AIGRID = (TT * 32) / 256;

    for (int l = 0; l < Lm; l++) {
        const __half* iw = w_aiw + (size_t)l * 3 * Dm * Dm;
        const float*  ib = attn_in_b  + (size_t)l * 3 * Dm;
        const __half* ow = w_aow + (size_t)l * Dm * Dm;
        const float*  ob = attn_out_b + (size_t)l * Dm;
        const __half* w1 = w_l1  + (size_t)l * FFm * Dm;
        const float*  b1 = lin1_b     + (size_t)l * FFm;
        const __half* w2 = w_l2  + (size_t)l * Dm * FFm;
        const float*  b2 = lin2_b     + (size_t)l * Dm;

        if (l == 0) {
            // deduped QKV: child rows (16384) + parent rows (256)
            hgemm_b3<false, true><<<dim3(QKV / 128, 130), NTHR, SMEMB>>>(
                pch, Dm, iw, ib, pqkv,
                pph, Dm, iw, ib, pqkv_p,
                pph, Dm, iw, ib, pqkv_p,      // unused segment
                128, 130, QKV, Dm);
            attn2<true><<<(NSEQ * Hm * 32) / 256, 256>>>(pqkv, pqkv_p, ppeq, ppek);
        } else {
            hgemm<false, true><<<gQKV, NTHR, SMEMB>>>(pxh, Dm, iw, ib, pqkv, QKV, Dm);
            attn2<false><<<(NSEQ * Hm * 32) / 256, 256>>>(
                pqkv, pqkv,
                ppeq + (size_t)l * 3 * Dm, ppek + (size_t)l * 3 * Dm);
        }
        // out-proj -> half delta, then x = inorm(x_src + delta)
        hgemm<false, true><<<gD , NTHR, SMEMB>>>(pah, Dm, ow, ob, pdh, Dm, Dm);
        if (l == 0)
            add_inorm<true , true><<<AIGRID, 256>>>(px, pxh, pdh, parent, child);
        else
            add_inorm<false, true><<<AIGRID, 256>>>(px, pxh, pdh, parent, child);
        // MLP
        hgemm<true , true><<<gM1, NTHR, SMEMB>>>(pxh,  Dm,  w1, b1, phid, FFm, Dm);
        hgemm<false, true><<<gD , NTHR, SMEMB>>>(phid, FFm, w2, b2, pdh,  Dm,  FFm);
        if (l + 1 < Lm)
            add_inorm<false, true ><<<AIGRID, 256>>>(px, pxh, pdh, parent, child);
        else
            add_inorm<false, false><<<AIGRID, 256>>>(px, pxh, pdh, parent, child);
    }

    // ---- join score path, then final output ----
    cudaStreamWaitEvent(0, evJoin, 0);
    final_out<<<(NSEQ * 32) / 256, 256>>>(out + NSEQ);
}

// round 16
// speedup vs baseline: 1.0396x; 1.0043x over previous
#include <cuda_runtime.h>
#include <cuda_fp16.h>
#include <math.h>
#include <stdint.h>

// ---------------------------------------------------------------------------
// Problem constants
// ---------------------------------------------------------------------------
namespace {
constexpr int Dm   = 768;
constexpr int FFm  = 3072;
constexpr int Hm   = 12;
constexpr int Lm   = 3;
constexpr int CSm  = 512;
constexpr int Bm   = 256;
constexpr int NSEQ = 16384;         // sequences of 2 tokens
constexpr int TT   = NSEQ * 2;      // 32768 tokens
constexpr float EPSf = 1e-5f;
constexpr int PS   = 72;            // smem row stride in halves (BK=64 + 8 pad)
constexpr int QKV  = 2304;          // fused QKV width
constexpr int NTHR = 256;           // gemm block size (8 warps) — R13 optimum
}

// ---------------------------------------------------------------------------
// Scratch (device globals; no runtime allocation allowed)
// ---------------------------------------------------------------------------
__device__ float g_x [TT * Dm];                    // fp32 residual state
__device__ float g_peq[Lm * 3 * Dm];               // pe @ Wq^T per (layer,role)
__device__ float g_pek[Lm * 3 * Dm];               // pe @ Wk^T per (layer,role)
__device__ __align__(16) __half g_sc  [TT * CSm];  // score outs (half)
__device__ __align__(16) __half g_qkvh[TT * QKV];  // fused QKV / half delta
__device__ __align__(16) __half g_xh  [TT * Dm];   // half copy of x
__device__ __align__(16) __half g_ah  [TT * Dm];   // attn-out
__device__ __align__(16) __half g_sh  [16640 * Dm];// score-path hiddens (own buf)
__device__ __align__(16) __half g_hidh[TT * FFm];  // MLP hidden (half)
__device__ __align__(16) __half g_wh  [24182784];  // all weights, half
__device__ __align__(16) __half g_ch  [TT * Dm];   // child, half
__device__ __align__(16) __half g_ph  [Bm * Dm];   // parent, half

__device__ __forceinline__ float gelu_f(float x) {
    return 0.5f * x * (1.0f + erff(x * 0.7071067811865475f));
}

__device__ __forceinline__ void cp_async16(uint32_t s, const void* g) {
    asm volatile("cp.async.cg.shared.global [%0], [%1], 16;\n" :: "r"(s), "l"(g));
}
__device__ __forceinline__ void cp_commit() {
    asm volatile("cp.async.commit_group;\n");
}
template <int N> __device__ __forceinline__ void cp_wait() {
    asm volatile("cp.async.wait_group %0;\n" :: "n"(N));
}
__device__ __forceinline__ void ldsm4(uint32_t& r0, uint32_t& r1,
                                      uint32_t& r2, uint32_t& r3, uint32_t addr) {
    asm volatile("ldmatrix.sync.aligned.m8n8.x4.shared.b16 {%0,%1,%2,%3}, [%4];"
                 : "=r"(r0), "=r"(r1), "=r"(r2), "=r"(r3) : "r"(addr));
}
__device__ __forceinline__ void mma16816(float* c, const uint32_t* a, const uint32_t* b) {
    asm volatile(
        "mma.sync.aligned.m16n8k16.row.col.f32.f16.f16.f32 "
        "{%0,%1,%2,%3}, {%4,%5,%6,%7}, {%8,%9}, {%0,%1,%2,%3};"
        : "+f"(c[0]), "+f"(c[1]), "+f"(c[2]), "+f"(c[3])
        : "r"(a[0]), "r"(a[1]), "r"(a[2]), "r"(a[3]), "r"(b[0]), "r"(b[1]));
}

// ---------------------------------------------------------------------------
// GEMM body: CTA 128x128, 8 warps (2m x 4n), warp tile 64x32, BK=64,
// m16n8k16 HMMA + ldmatrix.x4, 3-stage cp.async pipeline, 2 CTAs/SM.
// R13 optimum: ~40-44% tensor against crossbar ceiling. DO NOT TOUCH.
// ---------------------------------------------------------------------------
template <bool GELU, bool HALFOUT>
__device__ __forceinline__ void gemm_body(
    const __half* __restrict__ A, int lda,
    const __half* __restrict__ B, const float* __restrict__ bias,
    void* __restrict__ Cv, int ldc, int K, int bm, int bn, __half* sh)
{
    constexpr int BM = 128, BN = 128, BK = 64, ST = 3;
    constexpr int ASZ = BM * PS;
    constexpr int BSZ = BN * PS;
    __half* As = sh;
    __half* Bs = sh + ST * ASZ;

    const int tid  = threadIdx.x;
    const int lane = tid & 31;
    const int wid  = tid >> 5;
    const int wm   = wid >> 2;
    const int wn   = wid & 3;

    const int r0 = tid >> 3;
    const int cc = (tid & 7) * 8;
    const __half* Ap = A + (size_t)(bm + r0) * lda + cc;
    const __half* Bp = B + (size_t)(bn + r0) * K   + cc;

    const uint32_t sAbase = (uint32_t)__cvta_generic_to_shared(As);
    const uint32_t sBbase = (uint32_t)__cvta_generic_to_shared(Bs);
    const uint32_t sA = sAbase + (r0 * PS + cc) * 2;
    const uint32_t sB = sBbase + (r0 * PS + cc) * 2;

    const int nk = K / BK;

    auto issue = [&](int st, int kt) {
        const __half* Ag = Ap + kt * BK;
        const __half* Bg = Bp + kt * BK;
        uint32_t a = sA + st * (ASZ * 2);
        uint32_t b = sB + st * (BSZ * 2);
#pragma unroll
        for (int i = 0; i < 4; i++)
            cp_async16(a + i * 32 * PS * 2, Ag + (size_t)i * 32 * lda);
#pragma unroll
        for (int i = 0; i < 4; i++)
            cp_async16(b + i * 32 * PS * 2, Bg + (size_t)i * 32 * K);
        cp_commit();
    };

    float c[4][4][4];
#pragma unroll
    for (int mt = 0; mt < 4; mt++)
#pragma unroll
        for (int nt = 0; nt < 4; nt++)
#pragma unroll
            for (int j = 0; j < 4; j++) c[mt][nt][j] = 0.f;

    const int aOff = (wm * 64 + (lane & 15)) * PS + (lane >> 4) * 8;
    const int bOff = (wn * 32 + (lane & 7) + ((lane >> 4) & 1) * 8) * PS
                   + ((lane >> 3) & 1) * 8;

    issue(0, 0);
    issue(1, 1);

    for (int it = 0; it < nk; it++) {
        cp_wait<1>();
        __syncthreads();
        if (it + 2 < nk) issue((it + 2) % 3, it + 2);
        else             cp_commit();

        const int st = it % 3;
        const uint32_t aS = sAbase + (st * ASZ) * 2;
        const uint32_t bS = sBbase + (st * BSZ) * 2;
#pragma unroll
        for (int ks = 0; ks < 4; ks++) {
            uint32_t a[4][4], b[4][2];
#pragma unroll
            for (int mt = 0; mt < 4; mt++)
                ldsm4(a[mt][0], a[mt][1], a[mt][2], a[mt][3],
                      aS + (aOff + mt * 16 * PS + ks * 16) * 2);
#pragma unroll
            for (int np = 0; np < 2; np++)
                ldsm4(b[2 * np][0], b[2 * np][1], b[2 * np + 1][0], b[2 * np + 1][1],
                      bS + (bOff + np * 16 * PS + ks * 16) * 2);
#pragma unroll
            for (int mt = 0; mt < 4; mt++)
#pragma unroll
                for (int nt = 0; nt < 4; nt++)
                    mma16816(c[mt][nt], a[mt], b[nt]);
        }
    }

    const int g  = lane >> 2;
    const int tg = lane & 3;
#pragma unroll
    for (int mt = 0; mt < 4; mt++) {
        const int row = bm + wm * 64 + mt * 16 + g;
#pragma unroll
        for (int nt = 0; nt < 4; nt++) {
            const int col = bn + wn * 32 + nt * 8 + 2 * tg;
            const float bx = bias[col], by = bias[col + 1];
            float v0x = c[mt][nt][0] + bx, v0y = c[mt][nt][1] + by;
            float v1x = c[mt][nt][2] + bx, v1y = c[mt][nt][3] + by;
            if (GELU) {
                v0x = gelu_f(v0x); v0y = gelu_f(v0y);
                v1x = gelu_f(v1x); v1y = gelu_f(v1y);
            }
            if (HALFOUT) {
                __half* C = (__half*)Cv;
                *(__half2*)(C + (size_t)row * ldc + col)       = __floats2half2_rn(v0x, v0y);
                *(__half2*)(C + (size_t)(row + 8) * ldc + col) = __floats2half2_rn(v1x, v1y);
            } else {
                float* C = (float*)Cv;
                *(float2*)(C + (size_t)row * ldc + col)       = make_float2(v0x, v0y);
                *(float2*)(C + (size_t)(row + 8) * ldc + col) = make_float2(v1x, v1y);
            }
        }
    }
}

template <bool GELU, bool HALFOUT>
__global__ void __launch_bounds__(NTHR, 2) hgemm(
    const __half* __restrict__ A, int lda,
    const __half* __restrict__ B, const float* __restrict__ bias,
    void* __restrict__ Cv, int ldc, int K)
{
    extern __shared__ __half sh[];
    gemm_body<GELU, HALFOUT>(A, lda, B, bias, Cv, ldc, K,
                             blockIdx.y * 128, blockIdx.x * 128, sh);
}

// 3-segment batched GEMM: blockIdx.y range selects (A,lda,B,bias,C)
template <bool GELU, bool HALFOUT>
__global__ void __launch_bounds__(NTHR, 2) hgemm_b3(
    const __half* A0, int lda0, const __half* B0, const float* bias0, void* C0,
    const __half* A1, int lda1, const __half* B1, const float* bias1, void* C1,
    const __half* A2, int lda2, const __half* B2, const float* bias2, void* C2,
    int y1, int y2, int ldc, int K)
{
    extern __shared__ __half sh[];
    const int y = blockIdx.y;
    const __half* A; int lda; const __half* B; const float* bias; void* C; int ly;
    if (y < y1)      { A = A0; lda = lda0; B = B0; bias = bias0; C = C0; ly = y; }
    else if (y < y2) { A = A1; lda = lda1; B = B1; bias = bias1; C = C1; ly = y - y1; }
    else             { A = A2; lda = lda2; B = B2; bias = bias2; C = C2; ly = y - y2; }
    gemm_body<GELU, HALFOUT>(A, lda, B, bias, C, ldc, K,
                             ly * 128, blockIdx.x * 128, sh);
}

// ---------------------------------------------------------------------------
// Fused fp32 -> fp16 conversion for all segments (single launch)
// ---------------------------------------------------------------------------
struct CvtArgs {
    const float2* src[12];
    __half2*      dst[12];
    int           end[12];
};
__global__ void cvt_all(CvtArgs a, int total2)
{
    int i = blockIdx.x * blockDim.x + threadIdx.x;
    if (i >= total2) return;
    int s = 0;
#pragma unroll
    for (int k = 0; k < 11; k++) s += (i >= a.end[s]) ? 1 : 0;
    int base = s ? a.end[s - 1] : 0;
    float2 v = a.src[s][i - base];
    a.dst[s][i - base] = __floats2half2_rn(v.x, v.y);
}

// ---------------------------------------------------------------------------
// pe-projection biases
// ---------------------------------------------------------------------------
__global__ void peb(const float* __restrict__ pos_emb,
                    const __half* __restrict__ w_aiw,
                    float* __restrict__ peq, float* __restrict__ pek)
{
    int gw   = (blockIdx.x * blockDim.x + threadIdx.x) >> 5;
    int lane = threadIdx.x & 31;
    if (gw >= 2 * Lm * 3 * Dm) return;
    int d  = gw % Dm;
    int t  = gw / Dm;
    int r  = t % 3;
    int qk = (t / 3) % 2;
    int l  = t / 6;

    const __half* wrow = w_aiw + ((size_t)l * 3 * Dm + qk * Dm + d) * Dm;
    const float*  pe   = pos_emb + (size_t)(l * 4 + r) * Dm;
    float s = 0.f;
#pragma unroll 4
    for (int j = lane; j < Dm; j += 32) s += pe[j] * __half2float(wrow[j]);
#pragma unroll
    for (int o = 16; o; o >>= 1) s += __shfl_xor_sync(0xffffffffu, s, o);
    if (lane == 0)
        (qk ? pek : peq)[(l * 3 + r) * Dm + d] = s;
}

// ---------------------------------------------------------------------------
// 2x2 attention per (sequence, head). One warp per (n,h).
// ---------------------------------------------------------------------------
template <bool L1>
__global__ void attn2(const __half* __restrict__ qkv,
                      const __half* __restrict__ qkv_p,
                      const float* __restrict__ peq,
                      const float* __restrict__ pek)
{
    int gw   = (blockIdx.x * blockDim.x + threadIdx.x) >> 5;
    int lane = threadIdx.x & 31;
    if (gw >= NSEQ * Hm) return;
    int n = gw / Hm;
    int h = gw - n * Hm;

    const int pidx = h * 64 + 2 * lane;
    size_t b0, b1;
    const __half* src0;
    if (L1) {
        src0 = qkv_p;
        b0 = (size_t)(n >> 6) * QKV + pidx;
        b1 = (size_t)(n ^ 1) * QKV + pidx;
    } else {
        src0 = qkv;
        b0 = (size_t)(2 * n) * QKV + pidx;
        b1 = b0 + QKV;
    }
    const int r1 = 1 + (n & 1);

    float2 hq0 = __half22float2(*(const __half2*)(src0 + b0));
    float2 hk0 = __half22float2(*(const __half2*)(src0 + b0 + Dm));
    float2 v0  = __half22float2(*(const __half2*)(src0 + b0 + 2 * Dm));
    float2 hq1 = __half22float2(*(const __half2*)(qkv + b1));
    float2 hk1 = __half22float2(*(const __half2*)(qkv + b1 + Dm));
    float2 v1  = __half22float2(*(const __half2*)(qkv + b1 + 2 * Dm));

    float2 pq0 = *(const float2*)(peq + pidx);
    float2 pk0 = *(const float2*)(pek + pidx);
    float2 pq1 = *(const float2*)(peq + r1 * Dm + pidx);
    float2 pk1 = *(const float2*)(pek + r1 * Dm + pidx);

    float2 q0 = make_float2(hq0.x + pq0.x, hq0.y + pq0.y);
    float2 k0 = make_float2(hk0.x + pk0.x, hk0.y + pk0.y);
    float2 q1 = make_float2(hq1.x + pq1.x, hq1.y + pq1.y);
    float2 k1 = make_float2(hk1.x + pk1.x, hk1.y + pk1.y);

    float s00 = q0.x * k0.x + q0.y * k0.y;
    float s01 = q0.x * k1.x + q0.y * k1.y;
    float s10 = q1.x * k0.x + q1.y * k0.y;
    float s11 = q1.x * k1.x + q1.y * k1.y;
#pragma unroll
    for (int o = 16; o; o >>= 1) {
        s00 += __shfl_xor_sync(0xffffffffu, s00, o);
        s01 += __shfl_xor_sync(0xffffffffu, s01, o);
        s10 += __shfl_xor_sync(0xffffffffu, s10, o);
        s11 += __shfl_xor_sync(0xffffffffu, s11, o);
    }
    const float sc = 0.125f;
    s00 *= sc; s01 *= sc; s10 *= sc; s11 *= sc;

    float m0 = fmaxf(s00, s01), m1 = fmaxf(s10, s11);
    float e00 = __expf(s00 - m0), e01 = __expf(s01 - m0);
    float e10 = __expf(s10 - m1), e11 = __expf(s11 - m1);
    float r0 = 1.f / (e00 + e01), rr1 = 1.f / (e10 + e11);
    float a00 = e00 * r0, a01 = e01 * r0;
    float a10 = e10 * rr1, a11 = e11 * rr1;

    size_t vbase = (size_t)(2 * n) * Dm + pidx;
    *(__half2*)(g_ah + vbase) =
        __floats2half2_rn(a00 * v0.x + a01 * v1.x, a00 * v0.y + a01 * v1.y);
    *(__half2*)(g_ah + vbase + Dm) =
        __floats2half2_rn(a10 * v0.x + a11 * v1.x, a10 * v0.y + a11 * v1.y);
}

// ---------------------------------------------------------------------------
// Warp-reduce helper
// ---------------------------------------------------------------------------
__device__ __forceinline__ float wsum(float v) {
#pragma unroll
    for (int o = 16; o; o >>= 1) v += __shfl_xor_sync(0xffffffffu, v, o);
    return v;
}

// x = inorm(x_src + delta): one warp per row; delta fp16.
// FIRST: gather x_src directly from parent/child (build_x eliminated).
// WRITEH: also write the fp16 copy of the result.
template <bool FIRST, bool WRITEH>
__global__ void add_inorm(float* __restrict__ x, __half* __restrict__ xh,
                          const __half* __restrict__ delta,
                          const float* __restrict__ parent,
                          const float* __restrict__ child)
{
    int row  = (blockIdx.x * blockDim.x + threadIdx.x) >> 5;
    int lane = threadIdx.x & 31;
    if (row >= TT) return;
    size_t base = (size_t)row * Dm;

    const float4* xp;
    if (FIRST) {
        if ((row & 1) == 0)
            xp = (const float4*)(parent + (size_t)(row >> 7) * Dm);
        else
            xp = (const float4*)(child + (size_t)((row >> 1) ^ 1) * Dm);
    } else {
        xp = (const float4*)(x + base);
    }
    const __half2* dp = (const __half2*)(delta + base);

    float4 v[6];
    float s = 0.f;
#pragma unroll
    for (int i = 0; i < 6; i++) {
        float4 a  = xp[lane + 32 * i];
        float2 d0 = __half22float2(dp[(lane + 32 * i) * 2]);
        float2 d1 = __half22float2(dp[(lane + 32 * i) * 2 + 1]);
        v[i].x = a.x + d0.x; v[i].y = a.y + d0.y;
        v[i].z = a.z + d1.x; v[i].w = a.w + d1.y;
        s += v[i].x + v[i].y + v[i].z + v[i].w;
    }
    float mean = wsum(s) * (1.f / 768.f);
    float vs = 0.f;
#pragma unroll
    for (int i = 0; i < 6; i++) {
        float dx = v[i].x - mean, dy = v[i].y - mean;
        float dz = v[i].z - mean, dw = v[i].w - mean;
        vs += dx * dx + dy * dy + dz * dz + dw * dw;
    }
    float rs = rsqrtf(wsum(vs) * (1.f / 768.f) + EPSf);

    float4*  xo = (float4*)(x + base);
    __half2* ho = (__half2*)(xh + base);
#pragma unroll
    for (int i = 0; i < 6; i++) {
        float4 r;
        r.x = (v[i].x - mean) * rs; r.y = (v[i].y - mean) * rs;
        r.z = (v[i].z - mean) * rs; r.w = (v[i].w - mean) * rs;
        xo[lane + 32 * i] = r;
        if (WRITEH) {
            ho[(lane + 32 * i) * 2]     = __floats2half2_rn(r.x, r.y);
            ho[(lane + 32 * i) * 2 + 1] = __floats2half2_rn(r.z, r.w);
        }
    }
}

// ---------------------------------------------------------------------------
// Fused final stage: for each sequence n, compute
//   a = inorm(x[2n]   + delta[2n])      (last-layer MLP residual)
//   b = inorm(x[2n+1] + delta[2n+1])
//   out[n] = inorm(a + b)
// One warp per sequence; replaces the last add_inorm + final_out
// (saves a 100 MB store and a 200 MB load of g_x).
// ---------------------------------------------------------------------------
__global__ void last_fuse(const float* __restrict__ x,
                          const __half* __restrict__ delta,
                          float* __restrict__ out)
{
    int n    = (blockIdx.x * blockDim.x + threadIdx.x) >> 5;
    int lane = threadIdx.x & 31;
    if (n >= NSEQ) return;

    float4 acc[6];
#pragma unroll
    for (int t = 0; t < 2; t++) {
        size_t base = (size_t)(2 * n + t) * Dm;
        const float4*  xp = (const float4*)(x + base);
        const __half2* dp = (const __half2*)(delta + base);

        float4 v[6];
        float s = 0.f;
#pragma unroll
        for (int i = 0; i < 6; i++) {
            float4 a  = xp[lane + 32 * i];
            float2 d0 = __half22float2(dp[(lane + 32 * i) * 2]);
            float2 d1 = __half22float2(dp[(lane + 32 * i) * 2 + 1]);
            v[i].x = a.x + d0.x; v[i].y = a.y + d0.y;
            v[i].z = a.z + d1.x; v[i].w = a.w + d1.y;
            s += v[i].x + v[i].y + v[i].z + v[i].w;
        }
        float mean = wsum(s) * (1.f / 768.f);
        float vs = 0.f;
#pragma unroll
        for (int i = 0; i < 6; i++) {
            float dx = v[i].x - mean, dy = v[i].y - mean;
            float dz = v[i].z - mean, dw = v[i].w - mean;
            vs += dx * dx + dy * dy + dz * dz + dw * dw;
        }
        float rs = rsqrtf(wsum(vs) * (1.f / 768.f) + EPSf);

#pragma unroll
        for (int i = 0; i < 6; i++) {
            float4 r;
            r.x = (v[i].x - mean) * rs; r.y = (v[i].y - mean) * rs;
            r.z = (v[i].z - mean) * rs; r.w = (v[i].w - mean) * rs;
            if (t == 0) acc[i] = r;
            else {
                acc[i].x += r.x; acc[i].y += r.y;
                acc[i].z += r.z; acc[i].w += r.w;
            }
        }
    }

    // inorm of the pair sum
    float s = 0.f;
#pragma unroll
    for (int i = 0; i < 6; i++)
        s += acc[i].x + acc[i].y + acc[i].z + acc[i].w;
    float mean = wsum(s) * (1.f / 768.f);
    float vs = 0.f;
#pragma unroll
    for (int i = 0; i < 6; i++) {
        float dx = acc[i].x - mean, dy = acc[i].y - mean;
        float dz = acc[i].z - mean, dw = acc[i].w - mean;
        vs += dx * dx + dy * dy + dz * dz + dw * dw;
    }
    float rs = rsqrtf(wsum(vs) * (1.f / 768.f) + EPSf);

    float4* o = (float4*)(out + (size_t)n * Dm);
#pragma unroll
    for (int i = 0; i < 6; i++) {
        float4 r;
        r.x = (acc[i].x - mean) * rs; r.y = (acc[i].y - mean) * rs;
        r.z = (acc[i].z - mean) * rs; r.w = (acc[i].w - mean) * rs;
        o[lane + 32 * i] = r;
    }
}

// scores from half pc/lc/rc
__global__ void dot_scores(const __half* __restrict__ pc,
                           const __half* __restrict__ lc,
                           const __half* __restrict__ rc,
                           float* __restrict__ out)
{
    int gw   = (blockIdx.x * blockDim.x + threadIdx.x) >> 5;
    int lane = threadIdx.x & 31;
    if (gw >= NSEQ) return;
    int i     = gw >> 1;
    int which = gw & 1;
    int b     = i >> 5;
    const __half2* u = (const __half2*)(pc + (size_t)b * CSm);
    const __half2* w = (const __half2*)((which == 0 ? rc : lc) + (size_t)i * CSm);
    float s = 0.f;
#pragma unroll 4
    for (int j = lane; j < CSm / 2; j += 32) {
        float2 a = __half22float2(u[j]);
        float2 c = __half22float2(w[j]);
        s += a.x * c.x + a.y * c.y;
    }
    s = wsum(s);
    if (lane == 0) out[gw] = s * 0.044194173824159216f;
}

// ---------------------------------------------------------------------------
// Host launcher
// ---------------------------------------------------------------------------
static void* devptr(const void* sym)
{
    void* p = nullptr;
    cudaGetSymbolAddress(&p, sym);
    return p;
}

extern "C" void kernel_launch(void* const* d_in, const int* in_sizes, int n_in,
                              void* d_out, int out_size)
{
    (void)in_sizes; (void)n_in; (void)out_size;

    const float* parent     = (const float*)d_in[0];
    const float* child      = (const float*)d_in[1];
    const float* attn_in_w  = (const float*)d_in[4];
    const float* attn_in_b  = (const float*)d_in[5];
    const float* attn_out_w = (const float*)d_in[6];
    const float* attn_out_b = (const float*)d_in[7];
    const float* lin1_w     = (const float*)d_in[8];
    const float* lin1_b     = (const float*)d_in[9];
    const float* lin2_w     = (const float*)d_in[10];
    const float* lin2_b     = (const float*)d_in[11];
    const float* pos_emb    = (const float*)d_in[12];
    const float* parent_w1  = (const float*)d_in[13];
    const float* parent_b1  = (const float*)d_in[14];
    const float* parent_w2  = (const float*)d_in[15];
    const float* parent_b2  = (const float*)d_in[16];
    const float* left_w1    = (const float*)d_in[17];
    const float* left_b1    = (const float*)d_in[18];
    const float* left_w2    = (const float*)d_in[19];
    const float* left_b2    = (const float*)d_in[20];
    const float* right_w1   = (const float*)d_in[21];
    const float* right_b1   = (const float*)d_in[22];
    const float* right_w2   = (const float*)d_in[23];
    const float* right_b2   = (const float*)d_in[24];
    float* out = (float*)d_out;

    float*  px   = (float*) devptr(g_x);
    float*  ppeq = (float*) devptr(g_peq);
    float*  ppek = (float*) devptr(g_pek);
    __half* psc  = (__half*)devptr(g_sc);
    __half* pqkv = (__half*)devptr(g_qkvh);
    __half* pxh  = (__half*)devptr(g_xh);
    __half* pah  = (__half*)devptr(g_ah);
    __half* psh  = (__half*)devptr(g_sh);
    __half* phid = (__half*)devptr(g_hidh);
    __half* pwh  = (__half*)devptr(g_wh);
    __half* pch  = (__half*)devptr(g_ch);
    __half* pph  = (__half*)devptr(g_ph);

    constexpr int SMEMB = 3 * (128 + 128) * PS * 2;   // 110592 B -> 2 CTAs/SM
    static int attr_done = 0;
    static cudaStream_t s2 = nullptr;
    static cudaEvent_t evFork = nullptr, evJoin = nullptr;
    if (!attr_done) {
        cudaFuncSetAttribute(hgemm<false, true>,
                             cudaFuncAttributeMaxDynamicSharedMemorySize, SMEMB);
        cudaFuncSetAttribute(hgemm<true, true>,
                             cudaFuncAttributeMaxDynamicSharedMemorySize, SMEMB);
        cudaFuncSetAttribute(hgemm_b3<true, true>,
                             cudaFuncAttributeMaxDynamicSharedMemorySize, SMEMB);
        cudaFuncSetAttribute(hgemm_b3<false, true>,
                             cudaFuncAttributeMaxDynamicSharedMemorySize, SMEMB);
        cudaStreamCreateWithFlags(&s2, cudaStreamNonBlocking);
        cudaEventCreateWithFlags(&evFork, cudaEventDisableTiming);
        cudaEventCreateWithFlags(&evJoin, cudaEventDisableTiming);
        attr_done = 1;
    }

    // ---- fp16 conversion layout (offsets into g_wh) ----
    const int n_aiw = Lm * 3 * Dm * Dm;
    const int n_aow = Lm * Dm * Dm;
    const int n_l1  = Lm * FFm * Dm;
    const int n_l2  = Lm * Dm * FFm;
    const int n_w1  = Dm * Dm;
    const int n_w2  = CSm * Dm;

    __half* w_aiw = pwh;
    __half* w_aow = w_aiw + n_aiw;
    __half* w_l1  = w_aow + n_aow;
    __half* w_l2  = w_l1  + n_l1;
    __half* w_pw1 = w_l2  + n_l2;
    __half* w_pw2 = w_pw1 + n_w1;
    __half* w_lw1 = w_pw2 + n_w2;
    __half* w_lw2 = w_lw1 + n_w1;
    __half* w_rw1 = w_lw2 + n_w2;
    __half* w_rw2 = w_rw1 + n_w1;

    // single fused conversion launch
    {
        struct S { const float* s; __half* d; int n; };
        S segs[12] = {
            {attn_in_w,  w_aiw, n_aiw}, {attn_out_w, w_aow, n_aow},
            {lin1_w,     w_l1,  n_l1},  {lin2_w,     w_l2,  n_l2},
            {parent_w1,  w_pw1, n_w1},  {parent_w2,  w_pw2, n_w2},
            {left_w1,    w_lw1, n_w1},  {left_w2,    w_lw2, n_w2},
            {right_w1,   w_rw1, n_w1},  {right_w2,   w_rw2, n_w2},
            {child,      pch,   NSEQ * Dm}, {parent, pph,   Bm * Dm},
        };
        CvtArgs ca;
        int acc = 0;
        for (int i = 0; i < 12; i++) {
            ca.src[i] = (const float2*)segs[i].s;
            ca.dst[i] = (__half2*)segs[i].d;
            acc += segs[i].n / 2;
            ca.end[i] = acc;
        }
        cvt_all<<<(acc + 255) / 256, 256>>>(ca, acc);
    }

    // pe @ W{q,k}^T biases
    peb<<<(2 * Lm * 3 * Dm * 32) / 256, 256>>>(pos_emb, w_aiw, ppeq, ppek);

    // ---- fork: score path runs concurrently on s2 (independent buffers) ----
    cudaEventRecord(evFork, 0);
    cudaStreamWaitEvent(s2, evFork, 0);
    {
        __half* h_lft = psh;                              // 8192 x 768
        __half* h_rgt = psh + (size_t)8192 * Dm;
        __half* h_par = psh + (size_t)16384 * Dm;         // 256 x 768
        __half* o_lc  = psc;                              // 8192 x 512 (half)
        __half* o_rc  = psc + (size_t)8192 * CSm;
        __half* o_pc  = psc + (size_t)16384 * CSm;        // 256 x 512

        hgemm_b3<true, true><<<dim3(6, 130), NTHR, SMEMB, s2>>>(
            pch,      2 * Dm, w_lw1, left_b1,   h_lft,
            pch + Dm, 2 * Dm, w_rw1, right_b1,  h_rgt,
            pph,      Dm,     w_pw1, parent_b1, h_par,
            64, 128, Dm, Dm);
        hgemm_b3<false, true><<<dim3(4, 130), NTHR, SMEMB, s2>>>(
            h_lft, Dm, w_lw2, left_b2,   o_lc,
            h_rgt, Dm, w_rw2, right_b2,  o_rc,
            h_par, Dm, w_pw2, parent_b2, o_pc,
            64, 128, CSm, Dm);
        dot_scores<<<(NSEQ * 32) / 256, 256, 0, s2>>>(o_pc, o_lc, o_rc, out);
        cudaEventRecord(evJoin, s2);
    }

    // ---- 3 tree-transformer layers (main stream) ----
    dim3 gQKV(QKV / 128, TT / 128);    // (18, 256)
    dim3 gD  (Dm  / 128, TT / 128);    // (6, 256)
    dim3 gM1 (FFm / 128, TT / 128);    // (24, 256)
    __half* pqkv_p = pqkv + (size_t)NSEQ * QKV;   // parent QKV (layer 1)
    __half* pdh    = pqkv;                        // half delta (reuse after attn2)
    const int AIGRID = (TT * 32) / 256;

    for (int l = 0; l < Lm; l++) {
        const __half* iw = w_aiw + (size_t)l * 3 * Dm * Dm;
        const float*  ib = attn_in_b  + (size_t)l * 3 * Dm;
        const __half* ow = w_aow + (size_t)l * Dm * Dm;
        const float*  ob = attn_out_b + (size_t)l * Dm;
        const __half* w1 = w_l1  + (size_t)l * FFm * Dm;
        const float*  b1 = lin1_b     + (size_t)l * FFm;
        const __half* w2 = w_l2  + (size_t)l * Dm * FFm;
        const float*  b2 = lin2_b     + (size_t)l * Dm;

        if (l == 0) {
            // deduped QKV: child rows (16384) + parent rows (256)
            hgemm_b3<false, true><<<dim3(QKV / 128, 130), NTHR, SMEMB>>>(
                pch, Dm, iw, ib, pqkv,
                pph, Dm, iw, ib, pqkv_p,
                pph, Dm, iw, ib, pqkv_p,      // unused segment
                128, 130, QKV, Dm);
            attn2<true><<<(NSEQ * Hm * 32) / 256, 256>>>(pqkv, pqkv_p, ppeq, ppek);
        } else {
            hgemm<false, true><<<gQKV, NTHR, SMEMB>>>(pxh, Dm, iw, ib, pqkv, QKV, Dm);
            attn2<false><<<(NSEQ * Hm * 32) / 256, 256>>>(
                pqkv, pqkv,
                ppeq + (size_t)l * 3 * Dm, ppek + (size_t)l * 3 * Dm);
        }
        // out-proj -> half delta, then x = inorm(x_src + delta)
        hgemm<false, true><<<gD , NTHR, SMEMB>>>(pah, Dm, ow, ob, pdh, Dm, Dm);
        if (l == 0)
            add_inorm<true , true><<<AIGRID, 256>>>(px, pxh, pdh, parent, child);
        else
            add_inorm<false, true><<<AIGRID, 256>>>(px, pxh, pdh, parent, child);
        // MLP
        hgemm<true , true><<<gM1, NTHR, SMEMB>>>(pxh,  Dm,  w1, b1, phid, FFm, Dm);
        hgemm<false, true><<<gD , NTHR, SMEMB>>>(phid, FFm, w2, b2, pdh,  Dm,  FFm);
        if (l + 1 < Lm) {
            add_inorm<false, true><<<AIGRID, 256>>>(px, pxh, pdh, parent, child);
        } else {
            // fused: last add_inorm + pair-sum inorm -> out (after score join)
            cudaStreamWaitEvent(0, evJoin, 0);
            last_fuse<<<(NSEQ * 32) / 256, 256>>>(px, pdh, out + NSEQ);
        }
    }
}